// round 15
// baseline (speedup 1.0000x reference)
#include <cuda_runtime.h>
#include <cuda_fp16.h>
#include <float.h>

#define FULL 0xFFFFFFFFu

static constexpr int B = 4;
static constexpr int N = 8192;
static constexpr int M = 2048;
static constexpr int F = 256;
static constexpr int K = 16;
static constexpr int OUTC = 3 + F;  // 259

// KNN: 2 queries per warp, 16 warps/block -> 32 queries/block
static constexpr int KNNB = (B * M) / 32;              // 256 knn blocks
static constexpr int TRB  = B * (F / 32) * (N / 128);  // 2048 transpose tiles

// Scratch (device globals — no allocation allowed)
__device__ __half g_featT[(size_t)B * N * F];  // 16MB transposed features (B,N,F) fp16
__device__ int    g_idx[(size_t)B * M * K];
__device__ float  g_w[(size_t)B * M * K];

// ---------------------------------------------------------------------------
// Fused kernel: 512-thread blocks.
//   blocks [0, 256):     KNN — warp handles 2 queries; each staged 32-point
//                        tile (one LDS.128/lane) is scored for both queries
//                        (halves smem-crossbar traffic, the measured floor).
//                        The two per-tile ballots are independent (latency
//                        overlapped), and each query's insert path is
//                        byte-identical to the proven R9 code -> selection
//                        bit-exact.
//   blocks [256, 2304):  feature transpose (B,F,N)->(B,N,F) with fp32->fp16
//                        store (proven R14) — co-resident DRAM streaming.
// ---------------------------------------------------------------------------
__global__ __launch_bounds__(512) void fused_knn_transpose(
    const float* __restrict__ pc,     // (B,3,N)
    const float* __restrict__ qc,     // (B,3,M)
    const float* __restrict__ temperature,
    const float* __restrict__ feat,   // (B,F,N)
    float* __restrict__ out)          // (B,259,M)
{
    __shared__ __align__(16) unsigned char smem_raw[32768];

    if (blockIdx.x < KNNB) {
        // ===================== KNN (QPW=2) =====================
        float4* s_pts = (float4*)smem_raw;    // 2048 * 16B = 32KB

        const int tid  = threadIdx.x;
        const int lane = tid & 31;
        const int wid  = tid >> 5;
        const int b    = blockIdx.x >> 6;               // 64 blocks per batch
        const int m0   = ((blockIdx.x & 63) << 5) + wid * 2;  // first of 2 queries

        const float* pcb = pc + (size_t)b * 3 * N;
        const float* qcb = qc + (size_t)b * 3 * M;

        const float qx0 = qcb[m0],         qx1 = qcb[m0 + 1];
        const float qy0 = qcb[M + m0],     qy1 = qcb[M + m0 + 1];
        const float qz0 = qcb[2 * M + m0], qz1 = qcb[2 * M + m0 + 1];
        const float ax0 = -2.0f * qx0, ay0 = -2.0f * qy0, az0 = -2.0f * qz0;
        const float ax1 = -2.0f * qx1, ay1 = -2.0f * qy1, az1 = -2.0f * qz1;

        float kd0 = FLT_MAX, kd1 = FLT_MAX;   // warp-sorted lists
        int   ki0 = 0,       ki1 = 0;
        float thr0 = FLT_MAX, thr1 = FLT_MAX; // 16th-smallest (lazy)

        for (int c = 0; c < 4; ++c) {
            __syncthreads();
            for (int i = tid; i < 2048; i += 512) {
                int n = c * 2048 + i;
                float x = pcb[n];
                float y = pcb[N + n];
                float z = pcb[2 * N + n];
                s_pts[i] = make_float4(x, y, z, fmaf(x, x, fmaf(y, y, z * z)));
            }
            __syncthreads();

            #pragma unroll 4
            for (int t = 0; t < 64; ++t) {
                float4 p = s_pts[t * 32 + lane];
                float s0 = fmaf(ax0, p.x, p.w);
                s0 = fmaf(ay0, p.y, s0);
                s0 = fmaf(az0, p.z, s0);
                float s1 = fmaf(ax1, p.x, p.w);
                s1 = fmaf(ay1, p.y, s1);
                s1 = fmaf(az1, p.z, s1);
                // two INDEPENDENT ballots (issue back-to-back, overlap latency)
                unsigned mask0 = __ballot_sync(FULL, s0 < thr0);
                unsigned mask1 = __ballot_sync(FULL, s1 < thr1);
                if (mask0) {
                    int nbase = c * 2048 + t * 32;
                    do {
                        int src = __ffs(mask0) - 1;
                        mask0 &= mask0 - 1;
                        float cd = __shfl_sync(FULL, s0, src);
                        int   cn = nbase + src;
                        int pos = __popc(__ballot_sync(FULL, kd0 < cd));
                        float ud = __shfl_up_sync(FULL, kd0, 1);
                        int   ui = __shfl_up_sync(FULL, ki0, 1);
                        if (lane >= pos) {
                            kd0 = (lane == pos) ? cd : ud;
                            ki0 = (lane == pos) ? cn : ui;
                        }
                    } while (mask0);
                    thr0 = __shfl_sync(FULL, kd0, 15);
                }
                if (mask1) {
                    int nbase = c * 2048 + t * 32;
                    do {
                        int src = __ffs(mask1) - 1;
                        mask1 &= mask1 - 1;
                        float cd = __shfl_sync(FULL, s1, src);
                        int   cn = nbase + src;
                        int pos = __popc(__ballot_sync(FULL, kd1 < cd));
                        float ud = __shfl_up_sync(FULL, kd1, 1);
                        int   ui = __shfl_up_sync(FULL, ki1, 1);
                        if (lane >= pos) {
                            kd1 = (lane == pos) ? cd : ud;
                            ki1 = (lane == pos) ? cn : ui;
                        }
                    } while (mask1);
                    thr1 = __shfl_sync(FULL, kd1, 15);
                }
            }
        }

        // -------- epilogue per query (identical math to R9) --------
        float tv = *temperature;
        float sigma = fmaxf(tv * tv, 1e-4f);
        float inv_sigma = 1.0f / sigma;

        #pragma unroll
        for (int q = 0; q < 2; ++q) {
            float kd = q ? kd1 : kd0;
            int   ki = q ? ki1 : ki0;
            int   m  = m0 + q;

            float s0 = __shfl_sync(FULL, kd, 0);
            float ev = (lane < K) ? __expf((s0 - kd) * inv_sigma) : 0.0f;
            float sum = ev;
            #pragma unroll
            for (int o = 16; o; o >>= 1) sum += __shfl_xor_sync(FULL, sum, o);
            float w = ev / sum;

            float px = pcb[ki];
            float py = pcb[N + ki];
            float pz = pcb[2 * N + ki];
            float sx = w * px, sy = w * py, sz = w * pz;
            #pragma unroll
            for (int o = 16; o; o >>= 1) {
                sx += __shfl_xor_sync(FULL, sx, o);
                sy += __shfl_xor_sync(FULL, sy, o);
                sz += __shfl_xor_sync(FULL, sz, o);
            }
            if (lane == 0) {
                out[((size_t)b * OUTC + 0) * M + m] = sx;
                out[((size_t)b * OUTC + 1) * M + m] = sy;
                out[((size_t)b * OUTC + 2) * M + m] = sz;
            }
            if (lane < K) {
                size_t gq = (size_t)b * M + m;
                g_idx[gq * K + lane] = ki;
                g_w[gq * K + lane]   = w;
            }
        }
    } else {
        // ===================== transpose (fp16 store, proven) ==============
        // (B,F,N) -> (B,N,F); tile = 32 f x 128 n per block
        float (*tile)[129] = (float (*)[129])smem_raw;   // 32*129*4 = 16512B

        int t  = blockIdx.x - KNNB;         // 0..2047
        int b  = t >> 9;                    // 512 tiles per batch
        int r  = t & 511;
        int fb = r >> 6;                    // 0..7  (f block of 32)
        int nb = r & 63;                    // 0..63 (n block of 128)

        int tx = threadIdx.x & 127;         // n within tile
        int ty = threadIdx.x >> 7;          // 0..3
        const float* src = feat + ((size_t)b * F + fb * 32) * N + nb * 128;
        #pragma unroll
        for (int j = ty; j < 32; j += 4)
            tile[j][tx] = src[(size_t)j * N + tx];
        __syncthreads();

        int cx = threadIdx.x & 31;          // f within tile
        int cy = threadIdx.x >> 5;          // 0..15
        __half* dst = g_featT + ((size_t)b * N + nb * 128) * F + fb * 32;
        #pragma unroll
        for (int j = cy; j < 128; j += 16)
            dst[(size_t)j * F + cx] = __float2half(tile[cx][j]);
    }
}

// ---------------------------------------------------------------------------
// Feature propagation (R14-proven, byte-identical): 1024 threads = 32 warps =
// 16 queries, 2 warps/query; fp16 gathers (8B/lane/neighbor), fp32 accum.
// ---------------------------------------------------------------------------
__global__ __launch_bounds__(1024) void feat_kernel(float* __restrict__ out)
{
    __shared__ float so[16][260];

    const int lane   = threadIdx.x & 31;
    const int wid    = threadIdx.x >> 5;       // 0..31
    const int qlocal = wid >> 1;               // 0..15
    const int half   = wid & 1;                // 0/1 -> 128 features each
    const int b      = blockIdx.x >> 7;        // 128 blocks per batch
    const int m0     = (blockIdx.x & 127) * 16;
    const int m      = m0 + qlocal;
    const size_t gq  = (size_t)b * M + m;

    int   iv = 0;
    float wv = 0.0f;
    if (lane < K) {
        iv = g_idx[gq * K + lane];
        wv = g_w[gq * K + lane];
    }

    float4 acc = make_float4(0.f, 0.f, 0.f, 0.f);
    #pragma unroll
    for (int j = 0; j < K; ++j) {
        float wj = __shfl_sync(FULL, wv, j);
        int   ij = __shfl_sync(FULL, iv, j);
        const __half* basep =
            g_featT + ((size_t)b * N + ij) * F + half * 128;
        uint2 raw = *(const uint2*)(basep + lane * 4);   // 4 halves, 8B aligned
        __half2 h01 = *reinterpret_cast<__half2*>(&raw.x);
        __half2 h23 = *reinterpret_cast<__half2*>(&raw.y);
        float2 f01 = __half22float2(h01);
        float2 f23 = __half22float2(h23);
        acc.x = fmaf(wj, f01.x, acc.x);
        acc.y = fmaf(wj, f01.y, acc.y);
        acc.z = fmaf(wj, f23.x, acc.z);
        acc.w = fmaf(wj, f23.y, acc.w);
    }

    *(float4*)&so[qlocal][half * 128 + 4 * lane] = acc;
    __syncthreads();

    // warp wid writes f rows [wid*8, wid*8+8); lanes: 2 f x 16 mLocal
    #pragma unroll
    for (int r = 0; r < 4; ++r) {
        int f  = wid * 8 + r * 2 + (lane >> 4);
        int ml = lane & 15;
        out[((size_t)b * OUTC + 3 + f) * M + m0 + ml] = so[ml][f];
    }
}

// ---------------------------------------------------------------------------
extern "C" void kernel_launch(void* const* d_in, const int* in_sizes, int n_in,
                              void* d_out, int out_size)
{
    const float* pc   = (const float*)d_in[0];  // point_cloud (B,3,N)
    const float* qc   = (const float*)d_in[1];  // query_cloud (B,3,M)
    const float* feat = (const float*)d_in[2];  // point_features (B,F,N)
    const float* temp = (const float*)d_in[3];  // temperature scalar
    float* out = (float*)d_out;

    fused_knn_transpose<<<KNNB + TRB, 512>>>(pc, qc, temp, feat, out);
    feat_kernel<<<(B * M) / 16, 1024>>>(out);
}